// round 15
// baseline (speedup 1.0000x reference)
#include <cuda_runtime.h>
#include <cuda_fp16.h>

#define NN 50000
#define NN2 50176          // 196*256 padded rows (pad stays zero)
#define EE 800000
#define INF 128
#define NB 32
#define H_OFF 65536        // h starts after adj (256*256)
#define OUT_ELEMS 98304    // 256*256 + 256*128

__device__ __forceinline__ int graph_of(int n) { return (n * NB) / NN; }

// ---- scratch (module globals; zero-initialized, no runtime allocation) ----
__device__ float  g_Z[(size_t)NN * 128];      // fp32 embed columns
__device__ __half g_Zp[(size_t)NN * 256];     // fp16 pool logits
__device__ float  g_r[NN * 8];
__device__ int    g_counts[53248];            // zero at entry (static init; k_scan1 re-zeroes)
__device__ int    g_off[NN + 1];
__device__ int    g_cursor[NN];
__device__ int    g_bsum[64];
__device__ int2   g_sorted[EE];
__device__ __half g_Ah[(size_t)NN2 * 256];    // fp16 [x | neigh]; pad rows stay 0
__device__ __half g_Bh[384 * 256];            // fp16 W^T: [n][k]

// ================= helpers =================
__device__ __forceinline__ unsigned int smem_u32(const void* p) {
    unsigned int a;
    asm("{ .reg .u64 t; cvta.to.shared.u64 t, %1; cvt.u32.u64 %0, t; }" : "=r"(a) : "l"(p));
    return a;
}
#define GDC_LAUNCH() asm volatile("griddepcontrol.launch_dependents;")
#define GDC_WAIT()   asm volatile("griddepcontrol.wait;" ::: "memory")
#define CP_ASYNC16(dst, src) \
    asm volatile("cp.async.ca.shared.global [%0], [%1], 16;" :: "r"(dst), "l"(src) : "memory")
#define CP_COMMIT()  asm volatile("cp.async.commit_group;" ::: "memory")
#define CP_WAIT1()   asm volatile("cp.async.wait_group 1;" ::: "memory")
#define CP_WAIT0()   asm volatile("cp.async.wait_group 0;" ::: "memory")

__device__ __forceinline__ void ldmat4(unsigned* r, unsigned addr) {
    asm volatile("ldmatrix.sync.aligned.m8n8.x4.shared.b16 {%0,%1,%2,%3}, [%4];"
                 : "=r"(r[0]), "=r"(r[1]), "=r"(r[2]), "=r"(r[3]) : "r"(addr));
}
__device__ __forceinline__ void mma16n8k16(float* d, const unsigned* a, const unsigned* b) {
    asm volatile(
        "mma.sync.aligned.m16n8k16.row.col.f32.f16.f16.f32 "
        "{%0,%1,%2,%3}, {%4,%5,%6,%7}, {%8,%9}, {%0,%1,%2,%3};"
        : "+f"(d[0]), "+f"(d[1]), "+f"(d[2]), "+f"(d[3])
        : "r"(a[0]), "r"(a[1]), "r"(a[2]), "r"(a[3]), "r"(b[0]), "r"(b[1]));
}

// ---------------------------------------------------------------- init (vectorized regions)
#define T_OUT   24576
#define T_W     98304
#define T_X     800000
#define T_HIST  200000
#define T_TOTAL (T_OUT + T_W + T_X + T_HIST)
__global__ void k_init(float* __restrict__ out,
                       const float* __restrict__ We, const float* __restrict__ Wp,
                       const float* __restrict__ x, const int* __restrict__ ei) {
    GDC_LAUNCH();
    int i = blockIdx.x * blockDim.x + threadIdx.x;
    if (i < T_OUT) {
        reinterpret_cast<float4*>(out)[i] = make_float4(0.f, 0.f, 0.f, 0.f);
    } else if (i < T_OUT + T_W) {
        int idx = i - T_OUT;
        int k = idx & 255, n = idx >> 8;
        float v = (n < 128) ? We[k * 128 + n] : Wp[k * 256 + (n - 128)];
        g_Bh[n * 256 + k] = __float2half_rn(v);
    } else if (i < T_OUT + T_W + T_X) {
        int idx = i - T_OUT - T_W;          // 0..799999
        int row = idx >> 4, cg = idx & 15;  // 8 cols per task
        const float* xp = x + (size_t)row * 128 + cg * 8;
        float4 v0 = *reinterpret_cast<const float4*>(xp);
        float4 v1 = *reinterpret_cast<const float4*>(xp + 4);
        __half2 h0 = __floats2half2_rn(v0.x, v0.y);
        __half2 h1 = __floats2half2_rn(v0.z, v0.w);
        __half2 h2 = __floats2half2_rn(v1.x, v1.y);
        __half2 h3 = __floats2half2_rn(v1.z, v1.w);
        uint4 o;
        o.x = *reinterpret_cast<unsigned*>(&h0);
        o.y = *reinterpret_cast<unsigned*>(&h1);
        o.z = *reinterpret_cast<unsigned*>(&h2);
        o.w = *reinterpret_cast<unsigned*>(&h3);
        *reinterpret_cast<uint4*>(g_Ah + (size_t)row * 256 + cg * 8) = o;
    } else if (i < T_TOTAL) {
        int e = (i - T_OUT - T_W - T_X) * 4;
        int4 dv = *reinterpret_cast<const int4*>(ei + EE + e);
        atomicAdd(&g_counts[dv.x], 1);
        atomicAdd(&g_counts[dv.y], 1);
        atomicAdd(&g_counts[dv.z], 1);
        atomicAdd(&g_counts[dv.w], 1);
    }
}

// ---------------------------------------------------------------- scan stage 1
__global__ void k_scan1() {
    GDC_LAUNCH();
    int tid = threadIdx.x, lane = tid & 31, wid = tid >> 5;
    int idx = blockIdx.x * 1024 + tid;
    GDC_WAIT();
    int v = (idx < NN) ? g_counts[idx] : 0;
    if (idx < NN) g_counts[idx] = 0;
    int s = v;
    #pragma unroll
    for (int o = 1; o < 32; o <<= 1) {
        int u = __shfl_up_sync(0xFFFFFFFFu, s, o);
        if (lane >= o) s += u;
    }
    __shared__ int ws[32];
    if (lane == 31) ws[wid] = s;
    __syncthreads();
    if (wid == 0) {
        int u = ws[lane];
        #pragma unroll
        for (int o = 1; o < 32; o <<= 1) {
            int q = __shfl_up_sync(0xFFFFFFFFu, u, o);
            if (lane >= o) u += q;
        }
        ws[lane] = u;
    }
    __syncthreads();
    int excl = s - v + (wid ? ws[wid - 1] : 0);
    if (idx < NN) g_off[idx] = excl;
    if (tid == 1023) g_bsum[blockIdx.x] = excl + v;
}

// ---------------------------------------------------------------- scan stages 2+3 merged
__global__ void k_scan23() {
    GDC_LAUNCH();
    __shared__ int bo[64];
    __shared__ int w0s;
    int tid = threadIdx.x;
    GDC_WAIT();
    int v = 0, s = 0;
    if (tid < 64) {
        v = (tid < 49) ? g_bsum[tid] : 0;
        s = v;
        #pragma unroll
        for (int o = 1; o < 32; o <<= 1) {
            int u = __shfl_up_sync(0xFFFFFFFFu, s, o);
            if ((tid & 31) >= o) s += u;
        }
        if (tid == 31) w0s = s;
    }
    __syncthreads();
    if (tid < 64) bo[tid] = s - v + ((tid >= 32) ? w0s : 0);
    __syncthreads();
    int idx = blockIdx.x * 256 + tid;
    if (idx < NN) {
        int val = g_off[idx] + bo[idx >> 10];
        g_off[idx] = val;
        g_cursor[idx] = val;
    }
    if (idx == 0) g_off[NN] = EE;
}

// ---------------------------------------------------------------- scatter: 4 edges per thread
__global__ void k_scatter(const int* __restrict__ ei) {
    GDC_LAUNCH();
    int e = (blockIdx.x * 256 + threadIdx.x) * 4;
    if (e < EE) {
        int4 sv = *reinterpret_cast<const int4*>(ei + e);
        int4 dv = *reinterpret_cast<const int4*>(ei + EE + e);
        GDC_WAIT();
        int p0 = atomicAdd(&g_cursor[dv.x], 1);
        int p1 = atomicAdd(&g_cursor[dv.y], 1);
        int p2 = atomicAdd(&g_cursor[dv.z], 1);
        int p3 = atomicAdd(&g_cursor[dv.w], 1);
        g_sorted[p0] = make_int2(sv.x, dv.x);
        g_sorted[p1] = make_int2(sv.y, dv.y);
        g_sorted[p2] = make_int2(sv.z, dv.z);
        g_sorted[p3] = make_int2(sv.w, dv.w);
    }
}

// ---------------------------------------------------------------- mean aggregation (fp16 reads, MLP 8)
__global__ void k_neigh() {
    GDC_LAUNCH();
    int node = blockIdx.x * 8 + (threadIdx.x >> 5);
    if (node >= NN) return;
    int lane = threadIdx.x & 31;
    GDC_WAIT();
    int b = g_off[node], e = g_off[node + 1];
    float2 aa[8], bb[8];
    #pragma unroll
    for (int i = 0; i < 8; i++) { aa[i] = make_float2(0.f, 0.f); bb[i] = make_float2(0.f, 0.f); }
    int j = b;
    for (; j + 7 < e; j += 8) {
        uint2 u[8];
        #pragma unroll
        for (int i = 0; i < 8; i++) {
            int s0 = g_sorted[j + i].x;
            u[i] = *reinterpret_cast<const uint2*>(g_Ah + (size_t)s0 * 256 + lane * 4);
        }
        #pragma unroll
        for (int i = 0; i < 8; i++) {
            float2 f0 = __half22float2(*reinterpret_cast<__half2*>(&u[i].x));
            float2 f1 = __half22float2(*reinterpret_cast<__half2*>(&u[i].y));
            aa[i].x += f0.x; aa[i].y += f0.y;
            bb[i].x += f1.x; bb[i].y += f1.y;
        }
    }
    for (; j < e; j++) {
        int s0 = g_sorted[j].x;
        uint2 u0 = *reinterpret_cast<const uint2*>(g_Ah + (size_t)s0 * 256 + lane * 4);
        float2 f0 = __half22float2(*reinterpret_cast<__half2*>(&u0.x));
        float2 f1 = __half22float2(*reinterpret_cast<__half2*>(&u0.y));
        aa[0].x += f0.x; aa[0].y += f0.y;
        bb[0].x += f1.x; bb[0].y += f1.y;
    }
    float2 sa = make_float2(0.f, 0.f), sb = make_float2(0.f, 0.f);
    #pragma unroll
    for (int i = 0; i < 8; i++) {
        sa.x += aa[i].x; sa.y += aa[i].y;
        sb.x += bb[i].x; sb.y += bb[i].y;
    }
    float inv = 1.0f / (float)max(e - b, 1);
    __half2 h0 = __floats2half2_rn(sa.x * inv, sa.y * inv);
    __half2 h1 = __floats2half2_rn(sb.x * inv, sb.y * inv);
    uint2 o;
    o.x = *reinterpret_cast<unsigned*>(&h0);
    o.y = *reinterpret_cast<unsigned*>(&h1);
    *reinterpret_cast<uint2*>(g_Ah + (size_t)node * 256 + 128 + lane * 4) = o;
}

// ---------------------------------------------------------------- GEMM v4: fp16 m16n8k16 + ldmatrix
// CTA 256x128, K=256 in 8 chunks of 32 halves, 3-stage cp.async. SMEM 72KB.
#define SM_WORDS 18432
__global__ __launch_bounds__(256, 1) void k_gemm_mma(const float* __restrict__ be,
                                                     const float* __restrict__ bp) {
    GDC_LAUNCH();
    extern __shared__ unsigned int sm[];
    int tid = threadIdx.x, lane = tid & 31, wid = tid >> 5;
    int warp_m = wid >> 1, warp_n = wid & 1;       // 4 x 2 warps, warp tile 64x64
    int g = lane >> 2, t = lane & 3;
    int m0 = blockIdx.x * 256, bt = blockIdx.y;
    unsigned int sbase = smem_u32(sm);

    float acc[4][8][4];
    #pragma unroll
    for (int mt = 0; mt < 4; mt++)
        #pragma unroll
        for (int nt = 0; nt < 8; nt++)
            #pragma unroll
            for (int j = 0; j < 4; j++) acc[mt][nt][j] = 0.0f;

    auto load_chunk = [&](int c, int s) {
        unsigned int sa = sbase + s * 16384;
        unsigned int sb = sbase + 49152 + s * 8192;
        #pragma unroll
        for (int i = 0; i < 4; i++) {
            int e = tid + i * 256;
            int row = e >> 2, ch = e & 3;
            unsigned int soff = row * 64 + ((ch ^ ((row >> 1) & 3)) << 4);
            CP_ASYNC16(sa + soff, g_Ah + (size_t)(m0 + row) * 256 + c * 32 + ch * 8);
        }
        #pragma unroll
        for (int i = 0; i < 2; i++) {
            int e = tid + i * 256;
            int n = e >> 2, ch = e & 3;
            unsigned int soff = n * 64 + ((ch ^ ((n >> 1) & 3)) << 4);
            CP_ASYNC16(sb + soff, g_Bh + (size_t)(bt * 128 + n) * 256 + c * 32 + ch * 8);
        }
    };
    auto compute = [&](int s) {
        unsigned int Ab = sbase + s * 16384;
        unsigned int Bb = sbase + 49152 + s * 8192;
        #pragma unroll
        for (int ks = 0; ks < 2; ks++) {
            unsigned a[4][4], b[4][4];
            #pragma unroll
            for (int mt = 0; mt < 4; mt++) {
                int row = warp_m * 64 + mt * 16 + ((lane >> 3) & 1) * 8 + (lane & 7);
                int ch = 2 * ks + (lane >> 4);
                ldmat4(a[mt], Ab + row * 64 + ((ch ^ ((row >> 1) & 3)) << 4));
            }
            #pragma unroll
            for (int np = 0; np < 4; np++) {
                int n = warp_n * 64 + np * 16 + ((lane >> 4) << 3) + (lane & 7);
                int ch = 2 * ks + ((lane >> 3) & 1);
                ldmat4(b[np], Bb + n * 64 + ((ch ^ ((n >> 1) & 3)) << 4));
            }
            #pragma unroll
            for (int mt = 0; mt < 4; mt++)
                #pragma unroll
                for (int np = 0; np < 4; np++) {
                    mma16n8k16(acc[mt][2 * np],     a[mt], b[np]);
                    mma16n8k16(acc[mt][2 * np + 1], a[mt], b[np] + 2);
                }
        }
    };

    GDC_WAIT();
    load_chunk(0, 0); CP_COMMIT();
    load_chunk(1, 1); CP_COMMIT();
    #pragma unroll
    for (int c = 0; c < 8; c++) {
        if (c < 7) { CP_WAIT1(); } else { CP_WAIT0(); }
        __syncthreads();
        compute(c % 3);
        if (c + 2 < 8) { load_chunk(c + 2, (c + 2) % 3); CP_COMMIT(); }
    }

    // ---- epilogue: bias + store (embed fp32, logits fp16) ----
    __syncthreads();
    float* bsh = reinterpret_cast<float*>(sm);
    const float* bias = (bt == 0) ? be : bp + (bt - 1) * 128;
    if (tid < 128) bsh[tid] = bias[tid];
    __syncthreads();
    #pragma unroll
    for (int mt = 0; mt < 4; mt++) {
        int r0 = m0 + warp_m * 64 + mt * 16 + g;
        #pragma unroll
        for (int nt = 0; nt < 8; nt++) {
            int cloc = warp_n * 64 + nt * 8 + 2 * t;
            float bx = bsh[cloc], by = bsh[cloc + 1];
            if (bt == 0) {
                if (r0 < NN) {
                    float2 v = make_float2(acc[mt][nt][0] + bx, acc[mt][nt][1] + by);
                    *reinterpret_cast<float2*>(g_Z + (size_t)r0 * 128 + cloc) = v;
                }
                if (r0 + 8 < NN) {
                    float2 v = make_float2(acc[mt][nt][2] + bx, acc[mt][nt][3] + by);
                    *reinterpret_cast<float2*>(g_Z + (size_t)(r0 + 8) * 128 + cloc) = v;
                }
            } else {
                int cp = (bt - 1) * 128 + cloc;
                if (r0 < NN) {
                    __half2 h = __floats2half2_rn(acc[mt][nt][0] + bx, acc[mt][nt][1] + by);
                    *reinterpret_cast<__half2*>(g_Zp + (size_t)r0 * 256 + cp) = h;
                }
                if (r0 + 8 < NN) {
                    __half2 h = __floats2half2_rn(acc[mt][nt][2] + bx, acc[mt][nt][3] + by);
                    *reinterpret_cast<__half2*>(g_Zp + (size_t)(r0 + 8) * 256 + cp) = h;
                }
            }
        }
    }
}

// ---------------------------------------------------------------- per-node: softmax -> r, accumulate h (prefetched)
__global__ __launch_bounds__(128) void k_node(float* __restrict__ out) {
    GDC_LAUNCH();
    __shared__ float acc[4][2048];
    int tid = threadIdx.x, warp = tid >> 5, lane = tid & 31;
    int n0 = blockIdx.x * 128;
    int g0 = graph_of(n0);
    for (int i = tid; i < 4 * 2048; i += 128) (&acc[0][0])[i] = 0.0f;
    __syncthreads();
    float* ac = acc[warp];
    GDC_WAIT();

    int nfirst = n0 + warp * 32;
    uint4 lq; float4 ev;
    if (nfirst < NN) {
        lq = *reinterpret_cast<const uint4*>(g_Zp + (size_t)nfirst * 256 + lane * 8);
        ev = *reinterpret_cast<const float4*>(g_Z + (size_t)nfirst * 128 + lane * 4);
    }
    for (int it = 0; it < 32; it++) {
        int n = nfirst + it;
        if (n >= NN) break;
        uint4 cl = lq; float4 cev = ev;
        if (it < 31 && n + 1 < NN) {            // prefetch next row
            lq = *reinterpret_cast<const uint4*>(g_Zp + (size_t)(n + 1) * 256 + lane * 8);
            ev = *reinterpret_cast<const float4*>(g_Z + (size_t)(n + 1) * 128 + lane * 4);
        }
        float l[8];
        {
            float2 f0 = __half22float2(*reinterpret_cast<__half2*>(&cl.x));
            float2 f1 = __half22float2(*reinterpret_cast<__half2*>(&cl.y));
            float2 f2 = __half22float2(*reinterpret_cast<__half2*>(&cl.z));
            float2 f3 = __half22float2(*reinterpret_cast<__half2*>(&cl.w));
            l[0] = f0.x; l[1] = f0.y; l[2] = f1.x; l[3] = f1.y;
            l[4] = f2.x; l[5] = f2.y; l[6] = f3.x; l[7] = f3.y;
        }
        float mx = l[0];
        #pragma unroll
        for (int j = 1; j < 8; j++) mx = fmaxf(mx, l[j]);
        #pragma unroll
        for (int o = 16; o > 0; o >>= 1) mx = fmaxf(mx, __shfl_xor_sync(0xFFFFFFFFu, mx, o));
        float ex[8], s = 0.0f;
        #pragma unroll
        for (int j = 0; j < 8; j++) { ex[j] = expf(l[j] - mx); s += ex[j]; }
        #pragma unroll
        for (int o = 16; o > 0; o >>= 1) s += __shfl_xor_sync(0xFFFFFFFFu, s, o);
        float inv_s = 1.0f / s;
        float p[8], pm = -1e30f;
        #pragma unroll
        for (int j = 0; j < 8; j++) { p[j] = ex[j] * inv_s; pm = fmaxf(pm, p[j]); }
        float e2[8], se2 = 0.0f;
        #pragma unroll
        for (int j = 0; j < 8; j++) { e2[j] = expf(p[j] - pm); se2 += e2[j]; }
        float Zf = se2 + 248.0f * expf(-pm);
        float invZ = 1.0f / Zf;
        float invd = 1.0f / (se2 * invZ + 1e-13f);
        float r[8];
        #pragma unroll
        for (int j = 0; j < 8; j++) r[j] = e2[j] * invZ * invd;

        int gn = graph_of(n);
        if (lane == gn) {
            #pragma unroll
            for (int j = 0; j < 8; j++) g_r[n * 8 + j] = r[j];
        }
        float rb[8];
        #pragma unroll
        for (int j = 0; j < 8; j++) rb[j] = __shfl_sync(0xFFFFFFFFu, r[j], gn);

        int slot = gn - g0;
        float4* a4 = reinterpret_cast<float4*>(ac + slot * 1024) + lane;
        #pragma unroll
        for (int a = 0; a < 8; a++) {
            float ra = rb[a];
            float4 t = a4[a * 32];
            t.x = fmaf(ra, cev.x, t.x);
            t.y = fmaf(ra, cev.y, t.y);
            t.z = fmaf(ra, cev.z, t.z);
            t.w = fmaf(ra, cev.w, t.w);
            a4[a * 32] = t;
        }
    }
    __syncthreads();
    for (int idx = tid; idx < 2048; idx += 128) {
        float s = acc[0][idx] + acc[1][idx] + acc[2][idx] + acc[3][idx];
        int slot = idx >> 10, rest = idx & 1023, a = rest >> 7, c = rest & 127;
        int gg = g0 + slot;
        if (gg < NB && s != 0.0f)
            atomicAdd(out + H_OFF + ((gg << 3) + a) * 128 + c, s);
    }
}

// ---------------------------------------------------------------- per-edge adj: 4 edges per warp-iter
__global__ __launch_bounds__(256) void k_adj(float* __restrict__ out) {
    GDC_LAUNCH();
    __shared__ float acc[2 * 2048];
    int tid = threadIdx.x;
    for (int i = tid; i < 4096; i += 256) acc[i] = 0.0f;
    __syncthreads();
    GDC_WAIT();
    int e0 = blockIdx.x * 2048;
    int g0 = graph_of(g_sorted[e0].y);
    int warp = tid >> 5, lane = tid & 31;
    int aL = lane >> 2;
    int b0 = (lane & 3) * 2;
    int sel = lane >> 3;          // 0..3
    int li = lane & 7;

    for (int i = 0; i < 64; i++) {
        int e = e0 + warp * 256 + i * 4;
        if (e >= EE) break;
        int4 p0 = *reinterpret_cast<const int4*>(&g_sorted[e]);      // edges e, e+1
        int4 p1 = *reinterpret_cast<const int4*>(&g_sorted[e + 2]);  // edges e+2, e+3
        int idx1 = (sel == 0) ? p0.x : (sel == 1) ? p0.y : (sel == 2) ? p0.z : p0.w;
        int idx2 = (sel == 0) ? p1.x : (sel == 1) ? p1.y : (sel == 2) ? p1.z : p1.w;
        float v1 = g_r[idx1 * 8 + li];
        float v2 = g_r[idx2 * 8 + li];
        int src[4] = {p0.x, p0.z, p1.x, p1.z};
        int dst[4] = {p0.y, p0.w, p1.y, p1.w};
        float rs[4], rd0[4], rd1[4];
        rs[0]  = __shfl_sync(0xFFFFFFFFu, v1, aL);
        rd0[0] = __shfl_sync(0xFFFFFFFFu, v1, 8 + b0);
        rd1[0] = __shfl_sync(0xFFFFFFFFu, v1, 8 + b0 + 1);
        rs[1]  = __shfl_sync(0xFFFFFFFFu, v1, 16 + aL);
        rd0[1] = __shfl_sync(0xFFFFFFFFu, v1, 24 + b0);
        rd1[1] = __shfl_sync(0xFFFFFFFFu, v1, 24 + b0 + 1);
        rs[2]  = __shfl_sync(0xFFFFFFFFu, v2, aL);
        rd0[2] = __shfl_sync(0xFFFFFFFFu, v2, 8 + b0);
        rd1[2] = __shfl_sync(0xFFFFFFFFu, v2, 8 + b0 + 1);
        rs[3]  = __shfl_sync(0xFFFFFFFFu, v2, 16 + aL);
        rd0[3] = __shfl_sync(0xFFFFFFFFu, v2, 24 + b0);
        rd1[3] = __shfl_sync(0xFFFFFFFFu, v2, 24 + b0 + 1);
        #pragma unroll
        for (int k = 0; k < 4; k++) {
            int gs = graph_of(src[k]), gd = graph_of(dst[k]);
            int slot = gd - g0;
            int row = (gs << 3) + aL;
            float v0 = rs[k] * rd0[k], vv1 = rs[k] * rd1[k];
            if (slot >= 0 && slot < 2) {
                atomicAdd(&acc[slot * 2048 + row * 8 + b0],     v0);
                atomicAdd(&acc[slot * 2048 + row * 8 + b0 + 1], vv1);
            } else {
                atomicAdd(out + row * 256 + (gd << 3) + b0,     v0);
                atomicAdd(out + row * 256 + (gd << 3) + b0 + 1, vv1);
            }
        }
    }
    __syncthreads();
    for (int idx = tid; idx < 4096; idx += 256) {
        float s = acc[idx];
        int slot = idx >> 11, rest = idx & 2047, row = rest >> 3, bc = rest & 7;
        int gg = g0 + slot;
        if (gg < NB && s != 0.0f)
            atomicAdd(out + row * 256 + (gg << 3) + bc, s);
    }
}

// ---------------------------------------------------------------- PDL launch helper
template <typename F, typename... Args>
static void pdl_launch(F* k, dim3 grid, dim3 block, size_t smem, Args... args) {
    cudaLaunchConfig_t cfg = {};
    cfg.gridDim = grid;
    cfg.blockDim = block;
    cfg.dynamicSmemBytes = smem;
    cfg.stream = 0;
    cudaLaunchAttribute at[1];
    at[0].id = cudaLaunchAttributeProgrammaticStreamSerialization;
    at[0].val.programmaticStreamSerializationAllowed = 1;
    cfg.attrs = at;
    cfg.numAttrs = 1;
    cudaLaunchKernelEx(&cfg, k, args...);
}

// ---------------------------------------------------------------- launch
extern "C" void kernel_launch(void* const* d_in, const int* in_sizes, int n_in,
                              void* d_out, int out_size) {
    const float* x  = (const float*)d_in[0];
    const int*   ei = (const int*)d_in[1];
    const float* We = (const float*)d_in[3];
    const float* be = (const float*)d_in[4];
    const float* Wp = (const float*)d_in[5];
    const float* bp = (const float*)d_in[6];
    float* out = (float*)d_out;

    static int smem_set = 0;
    if (!smem_set) {
        cudaFuncSetAttribute(k_gemm_mma, cudaFuncAttributeMaxDynamicSharedMemorySize,
                             SM_WORDS * 4);
        smem_set = 1;
    }

    pdl_launch(k_init, dim3((T_TOTAL + 511) / 512), dim3(512), 0, out, We, Wp, x, ei);
    pdl_launch(k_scan1, dim3(49), dim3(1024), 0);
    pdl_launch(k_scan23, dim3((NN + 255) / 256), dim3(256), 0);
    pdl_launch(k_scatter, dim3((EE / 4 + 255) / 256), dim3(256), 0, ei);
    pdl_launch(k_neigh, dim3((NN + 7) / 8), dim3(256), 0);
    pdl_launch(k_gemm_mma, dim3(NN2 / 256, 3), dim3(256), (size_t)(SM_WORDS * 4), be, bp);
    pdl_launch(k_node, dim3((NN + 127) / 128), dim3(128), 0, out);
    pdl_launch(k_adj, dim3((EE + 2047) / 2048), dim3(256), 0, out);
}

// round 17
// speedup vs baseline: 1.1692x; 1.1692x over previous
#include <cuda_runtime.h>
#include <cuda_fp16.h>

#define NN 50000
#define NN2 50176          // 196*256 padded rows (pad stays zero)
#define EE 800000
#define INF 128
#define NB 32
#define H_OFF 65536        // h starts after adj (256*256)
#define OUT_ELEMS 98304    // 256*256 + 256*128

__device__ __forceinline__ int graph_of(int n) { return (n * NB) / NN; }

// ---- scratch (module globals; zero-initialized, no runtime allocation) ----
__device__ float  g_Z[(size_t)NN * 128];      // fp32 embed columns
__device__ __half g_Zp[(size_t)NN * 256];     // fp16 pool logits
__device__ float  g_r[NN * 8];
__device__ int    g_counts[53248];            // zero at entry (static init; k_scan1 re-zeroes)
__device__ int    g_off[NN + 1];
__device__ int    g_cursor[NN];
__device__ int    g_bsum[64];
__device__ int2   g_sorted[EE];
__device__ __half g_Ah[(size_t)NN2 * 256];    // fp16 [x | neigh]; pad rows stay 0
__device__ __half g_Bh[384 * 256];            // fp16 W^T: [n][k]

// ================= helpers =================
__device__ __forceinline__ unsigned int smem_u32(const void* p) {
    unsigned int a;
    asm("{ .reg .u64 t; cvta.to.shared.u64 t, %1; cvt.u32.u64 %0, t; }" : "=r"(a) : "l"(p));
    return a;
}
#define CP_ASYNC16(dst, src) \
    asm volatile("cp.async.ca.shared.global [%0], [%1], 16;" :: "r"(dst), "l"(src) : "memory")
#define CP_COMMIT()  asm volatile("cp.async.commit_group;" ::: "memory")
#define CP_WAIT1()   asm volatile("cp.async.wait_group 1;" ::: "memory")
#define CP_WAIT0()   asm volatile("cp.async.wait_group 0;" ::: "memory")

__device__ __forceinline__ void ldmat4(unsigned* r, unsigned addr) {
    asm volatile("ldmatrix.sync.aligned.m8n8.x4.shared.b16 {%0,%1,%2,%3}, [%4];"
                 : "=r"(r[0]), "=r"(r[1]), "=r"(r[2]), "=r"(r[3]) : "r"(addr));
}
__device__ __forceinline__ void mma16n8k16(float* d, const unsigned* a, const unsigned* b) {
    asm volatile(
        "mma.sync.aligned.m16n8k16.row.col.f32.f16.f16.f32 "
        "{%0,%1,%2,%3}, {%4,%5,%6,%7}, {%8,%9}, {%0,%1,%2,%3};"
        : "+f"(d[0]), "+f"(d[1]), "+f"(d[2]), "+f"(d[3])
        : "r"(a[0]), "r"(a[1]), "r"(a[2]), "r"(a[3]), "r"(b[0]), "r"(b[1]));
}

// ---------------------------------------------------------------- init (vectorized regions)
#define T_OUT   24576
#define T_W     98304
#define T_X     800000
#define T_HIST  200000
#define T_TOTAL (T_OUT + T_W + T_X + T_HIST)
__global__ void k_init(float* __restrict__ out,
                       const float* __restrict__ We, const float* __restrict__ Wp,
                       const float* __restrict__ x, const int* __restrict__ ei) {
    int i = blockIdx.x * blockDim.x + threadIdx.x;
    if (i < T_OUT) {
        reinterpret_cast<float4*>(out)[i] = make_float4(0.f, 0.f, 0.f, 0.f);
    } else if (i < T_OUT + T_W) {
        int idx = i - T_OUT;
        int k = idx & 255, n = idx >> 8;
        float v = (n < 128) ? We[k * 128 + n] : Wp[k * 256 + (n - 128)];
        g_Bh[n * 256 + k] = __float2half_rn(v);
    } else if (i < T_OUT + T_W + T_X) {
        int idx = i - T_OUT - T_W;          // 0..799999
        int row = idx >> 4, cg = idx & 15;  // 8 cols per task
        const float* xp = x + (size_t)row * 128 + cg * 8;
        float4 v0 = *reinterpret_cast<const float4*>(xp);
        float4 v1 = *reinterpret_cast<const float4*>(xp + 4);
        __half2 h0 = __floats2half2_rn(v0.x, v0.y);
        __half2 h1 = __floats2half2_rn(v0.z, v0.w);
        __half2 h2 = __floats2half2_rn(v1.x, v1.y);
        __half2 h3 = __floats2half2_rn(v1.z, v1.w);
        uint4 o;
        o.x = *reinterpret_cast<unsigned*>(&h0);
        o.y = *reinterpret_cast<unsigned*>(&h1);
        o.z = *reinterpret_cast<unsigned*>(&h2);
        o.w = *reinterpret_cast<unsigned*>(&h3);
        *reinterpret_cast<uint4*>(g_Ah + (size_t)row * 256 + cg * 8) = o;
    } else if (i < T_TOTAL) {
        int e = (i - T_OUT - T_W - T_X) * 4;
        int4 dv = *reinterpret_cast<const int4*>(ei + EE + e);
        atomicAdd(&g_counts[dv.x], 1);
        atomicAdd(&g_counts[dv.y], 1);
        atomicAdd(&g_counts[dv.z], 1);
        atomicAdd(&g_counts[dv.w], 1);
    }
}

// ---------------------------------------------------------------- scan stage 1
__global__ void k_scan1() {
    int tid = threadIdx.x, lane = tid & 31, wid = tid >> 5;
    int idx = blockIdx.x * 1024 + tid;
    int v = (idx < NN) ? g_counts[idx] : 0;
    if (idx < NN) g_counts[idx] = 0;
    int s = v;
    #pragma unroll
    for (int o = 1; o < 32; o <<= 1) {
        int u = __shfl_up_sync(0xFFFFFFFFu, s, o);
        if (lane >= o) s += u;
    }
    __shared__ int ws[32];
    if (lane == 31) ws[wid] = s;
    __syncthreads();
    if (wid == 0) {
        int u = ws[lane];
        #pragma unroll
        for (int o = 1; o < 32; o <<= 1) {
            int q = __shfl_up_sync(0xFFFFFFFFu, u, o);
            if (lane >= o) u += q;
        }
        ws[lane] = u;
    }
    __syncthreads();
    int excl = s - v + (wid ? ws[wid - 1] : 0);
    if (idx < NN) g_off[idx] = excl;
    if (tid == 1023) g_bsum[blockIdx.x] = excl + v;
}

// ---------------------------------------------------------------- scan stages 2+3 merged
__global__ void k_scan23() {
    __shared__ int bo[64];
    __shared__ int w0s;
    int tid = threadIdx.x;
    int v = 0, s = 0;
    if (tid < 64) {
        v = (tid < 49) ? g_bsum[tid] : 0;
        s = v;
        #pragma unroll
        for (int o = 1; o < 32; o <<= 1) {
            int u = __shfl_up_sync(0xFFFFFFFFu, s, o);
            if ((tid & 31) >= o) s += u;
        }
        if (tid == 31) w0s = s;
    }
    __syncthreads();
    if (tid < 64) bo[tid] = s - v + ((tid >= 32) ? w0s : 0);
    __syncthreads();
    int idx = blockIdx.x * 256 + tid;
    if (idx < NN) {
        int val = g_off[idx] + bo[idx >> 10];
        g_off[idx] = val;
        g_cursor[idx] = val;
    }
    if (idx == 0) g_off[NN] = EE;
}

// ---------------------------------------------------------------- scatter: 4 edges per thread
__global__ void k_scatter(const int* __restrict__ ei) {
    int e = (blockIdx.x * 256 + threadIdx.x) * 4;
    if (e < EE) {
        int4 sv = *reinterpret_cast<const int4*>(ei + e);
        int4 dv = *reinterpret_cast<const int4*>(ei + EE + e);
        int p0 = atomicAdd(&g_cursor[dv.x], 1);
        int p1 = atomicAdd(&g_cursor[dv.y], 1);
        int p2 = atomicAdd(&g_cursor[dv.z], 1);
        int p3 = atomicAdd(&g_cursor[dv.w], 1);
        g_sorted[p0] = make_int2(sv.x, dv.x);
        g_sorted[p1] = make_int2(sv.y, dv.y);
        g_sorted[p2] = make_int2(sv.z, dv.z);
        g_sorted[p3] = make_int2(sv.w, dv.w);
    }
}

// ---------------------------------------------------------------- mean aggregation (fp16 reads, MLP 8)
__global__ void k_neigh() {
    int node = blockIdx.x * 8 + (threadIdx.x >> 5);
    if (node >= NN) return;
    int lane = threadIdx.x & 31;
    int b = g_off[node], e = g_off[node + 1];
    float2 aa[8], bb[8];
    #pragma unroll
    for (int i = 0; i < 8; i++) { aa[i] = make_float2(0.f, 0.f); bb[i] = make_float2(0.f, 0.f); }
    int j = b;
    for (; j + 7 < e; j += 8) {
        uint2 u[8];
        #pragma unroll
        for (int i = 0; i < 8; i++) {
            int s0 = g_sorted[j + i].x;
            u[i] = *reinterpret_cast<const uint2*>(g_Ah + (size_t)s0 * 256 + lane * 4);
        }
        #pragma unroll
        for (int i = 0; i < 8; i++) {
            float2 f0 = __half22float2(*reinterpret_cast<__half2*>(&u[i].x));
            float2 f1 = __half22float2(*reinterpret_cast<__half2*>(&u[i].y));
            aa[i].x += f0.x; aa[i].y += f0.y;
            bb[i].x += f1.x; bb[i].y += f1.y;
        }
    }
    for (; j < e; j++) {
        int s0 = g_sorted[j].x;
        uint2 u0 = *reinterpret_cast<const uint2*>(g_Ah + (size_t)s0 * 256 + lane * 4);
        float2 f0 = __half22float2(*reinterpret_cast<__half2*>(&u0.x));
        float2 f1 = __half22float2(*reinterpret_cast<__half2*>(&u0.y));
        aa[0].x += f0.x; aa[0].y += f0.y;
        bb[0].x += f1.x; bb[0].y += f1.y;
    }
    float2 sa = make_float2(0.f, 0.f), sb = make_float2(0.f, 0.f);
    #pragma unroll
    for (int i = 0; i < 8; i++) {
        sa.x += aa[i].x; sa.y += aa[i].y;
        sb.x += bb[i].x; sb.y += bb[i].y;
    }
    float inv = 1.0f / (float)max(e - b, 1);
    __half2 h0 = __floats2half2_rn(sa.x * inv, sa.y * inv);
    __half2 h1 = __floats2half2_rn(sb.x * inv, sb.y * inv);
    uint2 o;
    o.x = *reinterpret_cast<unsigned*>(&h0);
    o.y = *reinterpret_cast<unsigned*>(&h1);
    *reinterpret_cast<uint2*>(g_Ah + (size_t)node * 256 + 128 + lane * 4) = o;
}

// ---------------------------------------------------------------- GEMM v4: fp16 m16n8k16 + ldmatrix
// CTA 256x128, K=256 in 8 chunks of 32 halves, 3-stage cp.async. SMEM 72KB.
#define SM_WORDS 18432
__global__ __launch_bounds__(256, 1) void k_gemm_mma(const float* __restrict__ be,
                                                     const float* __restrict__ bp) {
    extern __shared__ unsigned int sm[];
    int tid = threadIdx.x, lane = tid & 31, wid = tid >> 5;
    int warp_m = wid >> 1, warp_n = wid & 1;       // 4 x 2 warps, warp tile 64x64
    int g = lane >> 2, t = lane & 3;
    int m0 = blockIdx.x * 256, bt = blockIdx.y;
    unsigned int sbase = smem_u32(sm);

    float acc[4][8][4];
    #pragma unroll
    for (int mt = 0; mt < 4; mt++)
        #pragma unroll
        for (int nt = 0; nt < 8; nt++)
            #pragma unroll
            for (int j = 0; j < 4; j++) acc[mt][nt][j] = 0.0f;

    auto load_chunk = [&](int c, int s) {
        unsigned int sa = sbase + s * 16384;
        unsigned int sb = sbase + 49152 + s * 8192;
        #pragma unroll
        for (int i = 0; i < 4; i++) {
            int e = tid + i * 256;
            int row = e >> 2, ch = e & 3;
            unsigned int soff = row * 64 + ((ch ^ ((row >> 1) & 3)) << 4);
            CP_ASYNC16(sa + soff, g_Ah + (size_t)(m0 + row) * 256 + c * 32 + ch * 8);
        }
        #pragma unroll
        for (int i = 0; i < 2; i++) {
            int e = tid + i * 256;
            int n = e >> 2, ch = e & 3;
            unsigned int soff = n * 64 + ((ch ^ ((n >> 1) & 3)) << 4);
            CP_ASYNC16(sb + soff, g_Bh + (size_t)(bt * 128 + n) * 256 + c * 32 + ch * 8);
        }
    };
    auto compute = [&](int s) {
        unsigned int Ab = sbase + s * 16384;
        unsigned int Bb = sbase + 49152 + s * 8192;
        #pragma unroll
        for (int ks = 0; ks < 2; ks++) {
            unsigned a[4][4], b[4][4];
            #pragma unroll
            for (int mt = 0; mt < 4; mt++) {
                int row = warp_m * 64 + mt * 16 + ((lane >> 3) & 1) * 8 + (lane & 7);
                int ch = 2 * ks + (lane >> 4);
                ldmat4(a[mt], Ab + row * 64 + ((ch ^ ((row >> 1) & 3)) << 4));
            }
            #pragma unroll
            for (int np = 0; np < 4; np++) {
                int n = warp_n * 64 + np * 16 + ((lane >> 4) << 3) + (lane & 7);
                int ch = 2 * ks + ((lane >> 3) & 1);
                ldmat4(b[np], Bb + n * 64 + ((ch ^ ((n >> 1) & 3)) << 4));
            }
            #pragma unroll
            for (int mt = 0; mt < 4; mt++)
                #pragma unroll
                for (int np = 0; np < 4; np++) {
                    mma16n8k16(acc[mt][2 * np],     a[mt], b[np]);
                    mma16n8k16(acc[mt][2 * np + 1], a[mt], b[np] + 2);
                }
        }
    };

    load_chunk(0, 0); CP_COMMIT();
    load_chunk(1, 1); CP_COMMIT();
    #pragma unroll
    for (int c = 0; c < 8; c++) {
        if (c < 7) { CP_WAIT1(); } else { CP_WAIT0(); }
        __syncthreads();
        compute(c % 3);
        if (c + 2 < 8) { load_chunk(c + 2, (c + 2) % 3); CP_COMMIT(); }
    }

    // ---- epilogue: bias + store (embed fp32, logits fp16) ----
    __syncthreads();
    float* bsh = reinterpret_cast<float*>(sm);
    const float* bias = (bt == 0) ? be : bp + (bt - 1) * 128;
    if (tid < 128) bsh[tid] = bias[tid];
    __syncthreads();
    #pragma unroll
    for (int mt = 0; mt < 4; mt++) {
        int r0 = m0 + warp_m * 64 + mt * 16 + g;
        #pragma unroll
        for (int nt = 0; nt < 8; nt++) {
            int cloc = warp_n * 64 + nt * 8 + 2 * t;
            float bx = bsh[cloc], by = bsh[cloc + 1];
            if (bt == 0) {
                if (r0 < NN) {
                    float2 v = make_float2(acc[mt][nt][0] + bx, acc[mt][nt][1] + by);
                    *reinterpret_cast<float2*>(g_Z + (size_t)r0 * 128 + cloc) = v;
                }
                if (r0 + 8 < NN) {
                    float2 v = make_float2(acc[mt][nt][2] + bx, acc[mt][nt][3] + by);
                    *reinterpret_cast<float2*>(g_Z + (size_t)(r0 + 8) * 128 + cloc) = v;
                }
            } else {
                int cp = (bt - 1) * 128 + cloc;
                if (r0 < NN) {
                    __half2 h = __floats2half2_rn(acc[mt][nt][0] + bx, acc[mt][nt][1] + by);
                    *reinterpret_cast<__half2*>(g_Zp + (size_t)r0 * 256 + cp) = h;
                }
                if (r0 + 8 < NN) {
                    __half2 h = __floats2half2_rn(acc[mt][nt][2] + bx, acc[mt][nt][3] + by);
                    *reinterpret_cast<__half2*>(g_Zp + (size_t)(r0 + 8) * 256 + cp) = h;
                }
            }
        }
    }
}

// ---------------------------------------------------------------- per-node: softmax -> r, accumulate h (prefetched)
__global__ __launch_bounds__(128) void k_node(float* __restrict__ out) {
    __shared__ float acc[4][2048];
    int tid = threadIdx.x, warp = tid >> 5, lane = tid & 31;
    int n0 = blockIdx.x * 128;
    int g0 = graph_of(n0);
    for (int i = tid; i < 4 * 2048; i += 128) (&acc[0][0])[i] = 0.0f;
    __syncthreads();
    float* ac = acc[warp];

    int nfirst = n0 + warp * 32;
    uint4 lq; float4 ev;
    if (nfirst < NN) {
        lq = *reinterpret_cast<const uint4*>(g_Zp + (size_t)nfirst * 256 + lane * 8);
        ev = *reinterpret_cast<const float4*>(g_Z + (size_t)nfirst * 128 + lane * 4);
    }
    for (int it = 0; it < 32; it++) {
        int n = nfirst + it;
        if (n >= NN) break;
        uint4 cl = lq; float4 cev = ev;
        if (it < 31 && n + 1 < NN) {            // prefetch next row
            lq = *reinterpret_cast<const uint4*>(g_Zp + (size_t)(n + 1) * 256 + lane * 8);
            ev = *reinterpret_cast<const float4*>(g_Z + (size_t)(n + 1) * 128 + lane * 4);
        }
        float l[8];
        {
            float2 f0 = __half22float2(*reinterpret_cast<__half2*>(&cl.x));
            float2 f1 = __half22float2(*reinterpret_cast<__half2*>(&cl.y));
            float2 f2 = __half22float2(*reinterpret_cast<__half2*>(&cl.z));
            float2 f3 = __half22float2(*reinterpret_cast<__half2*>(&cl.w));
            l[0] = f0.x; l[1] = f0.y; l[2] = f1.x; l[3] = f1.y;
            l[4] = f2.x; l[5] = f2.y; l[6] = f3.x; l[7] = f3.y;
        }
        float mx = l[0];
        #pragma unroll
        for (int j = 1; j < 8; j++) mx = fmaxf(mx, l[j]);
        #pragma unroll
        for (int o = 16; o > 0; o >>= 1) mx = fmaxf(mx, __shfl_xor_sync(0xFFFFFFFFu, mx, o));
        float ex[8], s = 0.0f;
        #pragma unroll
        for (int j = 0; j < 8; j++) { ex[j] = expf(l[j] - mx); s += ex[j]; }
        #pragma unroll
        for (int o = 16; o > 0; o >>= 1) s += __shfl_xor_sync(0xFFFFFFFFu, s, o);
        float inv_s = 1.0f / s;
        float p[8], pm = -1e30f;
        #pragma unroll
        for (int j = 0; j < 8; j++) { p[j] = ex[j] * inv_s; pm = fmaxf(pm, p[j]); }
        float e2[8], se2 = 0.0f;
        #pragma unroll
        for (int j = 0; j < 8; j++) { e2[j] = expf(p[j] - pm); se2 += e2[j]; }
        float Zf = se2 + 248.0f * expf(-pm);
        float invZ = 1.0f / Zf;
        float invd = 1.0f / (se2 * invZ + 1e-13f);
        float r[8];
        #pragma unroll
        for (int j = 0; j < 8; j++) r[j] = e2[j] * invZ * invd;

        int gn = graph_of(n);
        if (lane == gn) {
            #pragma unroll
            for (int j = 0; j < 8; j++) g_r[n * 8 + j] = r[j];
        }
        float rb[8];
        #pragma unroll
        for (int j = 0; j < 8; j++) rb[j] = __shfl_sync(0xFFFFFFFFu, r[j], gn);

        int slot = gn - g0;
        float4* a4 = reinterpret_cast<float4*>(ac + slot * 1024) + lane;
        #pragma unroll
        for (int a = 0; a < 8; a++) {
            float ra = rb[a];
            float4 t = a4[a * 32];
            t.x = fmaf(ra, cev.x, t.x);
            t.y = fmaf(ra, cev.y, t.y);
            t.z = fmaf(ra, cev.z, t.z);
            t.w = fmaf(ra, cev.w, t.w);
            a4[a * 32] = t;
        }
    }
    __syncthreads();
    for (int idx = tid; idx < 2048; idx += 128) {
        float s = acc[0][idx] + acc[1][idx] + acc[2][idx] + acc[3][idx];
        int slot = idx >> 10, rest = idx & 1023, a = rest >> 7, c = rest & 127;
        int gg = g0 + slot;
        if (gg < NB && s != 0.0f)
            atomicAdd(out + H_OFF + ((gg << 3) + a) * 128 + c, s);
    }
}

// ---------------------------------------------------------------- per-edge adj: 4 edges per warp-iter
__global__ __launch_bounds__(256) void k_adj(float* __restrict__ out) {
    __shared__ float acc[2 * 2048];
    int tid = threadIdx.x;
    for (int i = tid; i < 4096; i += 256) acc[i] = 0.0f;
    __syncthreads();
    int e0 = blockIdx.x * 2048;
    int g0 = graph_of(g_sorted[e0].y);
    int warp = tid >> 5, lane = tid & 31;
    int aL = lane >> 2;
    int b0 = (lane & 3) * 2;
    int sel = lane >> 3;          // 0..3
    int li = lane & 7;

    for (int i = 0; i < 64; i++) {
        int e = e0 + warp * 256 + i * 4;
        if (e >= EE) break;
        int4 p0 = *reinterpret_cast<const int4*>(&g_sorted[e]);      // edges e, e+1
        int4 p1 = *reinterpret_cast<const int4*>(&g_sorted[e + 2]);  // edges e+2, e+3
        int idx1 = (sel == 0) ? p0.x : (sel == 1) ? p0.y : (sel == 2) ? p0.z : p0.w;
        int idx2 = (sel == 0) ? p1.x : (sel == 1) ? p1.y : (sel == 2) ? p1.z : p1.w;
        float v1 = g_r[idx1 * 8 + li];
        float v2 = g_r[idx2 * 8 + li];
        int src[4] = {p0.x, p0.z, p1.x, p1.z};
        int dst[4] = {p0.y, p0.w, p1.y, p1.w};
        float rs[4], rd0[4], rd1[4];
        rs[0]  = __shfl_sync(0xFFFFFFFFu, v1, aL);
        rd0[0] = __shfl_sync(0xFFFFFFFFu, v1, 8 + b0);
        rd1[0] = __shfl_sync(0xFFFFFFFFu, v1, 8 + b0 + 1);
        rs[1]  = __shfl_sync(0xFFFFFFFFu, v1, 16 + aL);
        rd0[1] = __shfl_sync(0xFFFFFFFFu, v1, 24 + b0);
        rd1[1] = __shfl_sync(0xFFFFFFFFu, v1, 24 + b0 + 1);
        rs[2]  = __shfl_sync(0xFFFFFFFFu, v2, aL);
        rd0[2] = __shfl_sync(0xFFFFFFFFu, v2, 8 + b0);
        rd1[2] = __shfl_sync(0xFFFFFFFFu, v2, 8 + b0 + 1);
        rs[3]  = __shfl_sync(0xFFFFFFFFu, v2, 16 + aL);
        rd0[3] = __shfl_sync(0xFFFFFFFFu, v2, 24 + b0);
        rd1[3] = __shfl_sync(0xFFFFFFFFu, v2, 24 + b0 + 1);
        #pragma unroll
        for (int k = 0; k < 4; k++) {
            int gs = graph_of(src[k]), gd = graph_of(dst[k]);
            int slot = gd - g0;
            int row = (gs << 3) + aL;
            float v0 = rs[k] * rd0[k], vv1 = rs[k] * rd1[k];
            if (slot >= 0 && slot < 2) {
                atomicAdd(&acc[slot * 2048 + row * 8 + b0],     v0);
                atomicAdd(&acc[slot * 2048 + row * 8 + b0 + 1], vv1);
            } else {
                atomicAdd(out + row * 256 + (gd << 3) + b0,     v0);
                atomicAdd(out + row * 256 + (gd << 3) + b0 + 1, vv1);
            }
        }
    }
    __syncthreads();
    for (int idx = tid; idx < 4096; idx += 256) {
        float s = acc[idx];
        int slot = idx >> 11, rest = idx & 2047, row = rest >> 3, bc = rest & 7;
        int gg = g0 + slot;
        if (gg < NB && s != 0.0f)
            atomicAdd(out + row * 256 + (gg << 3) + bc, s);
    }
}

// ---------------------------------------------------------------- launch
extern "C" void kernel_launch(void* const* d_in, const int* in_sizes, int n_in,
                              void* d_out, int out_size) {
    const float* x  = (const float*)d_in[0];
    const int*   ei = (const int*)d_in[1];
    const float* We = (const float*)d_in[3];
    const float* be = (const float*)d_in[4];
    const float* Wp = (const float*)d_in[5];
    const float* bp = (const float*)d_in[6];
    float* out = (float*)d_out;

    static int smem_set = 0;
    if (!smem_set) {
        cudaFuncSetAttribute(k_gemm_mma, cudaFuncAttributeMaxDynamicSharedMemorySize,
                             SM_WORDS * 4);
        smem_set = 1;
    }

    k_init<<<(T_TOTAL + 511) / 512, 512>>>(out, We, Wp, x, ei);
    k_scan1<<<49, 1024>>>();
    k_scan23<<<(NN + 255) / 256, 256>>>();
    k_scatter<<<(EE / 4 + 255) / 256, 256>>>(ei);
    k_neigh<<<(NN + 7) / 8, 256>>>();
    dim3 gg(NN2 / 256, 3);
    k_gemm_mma<<<gg, 256, SM_WORDS * 4>>>(be, bp);
    k_node<<<(NN + 127) / 128, 128>>>(out);
    k_adj<<<(EE + 2047) / 2048, 256>>>(out);
}